// round 7
// baseline (speedup 1.0000x reference)
#include <cuda_runtime.h>
#include <cuda_bf16.h>

#define DEV_INLINE __device__ __forceinline__
constexpr int BATCH = 4;
constexpr int NB = 148;          // persistent grid: one block per SM (<= SM count)
constexpr int NT = 512;          // threads per block
constexpr int NW = NB * (NT / 32);

// ---------------- buffer layout (floats) ----------------------------------
// NCHW padded: rows S+2, row-stride S+4. NHWC padded: [B][S+2][S+2][CST].
constexpr int OFF_X    = 0;                         // [4][3][34][36]
constexpr int SZ_X     = BATCH * 3 * 34 * 36;
constexpr int OFF_32A  = OFF_X + SZ_X;              // cap 64
constexpr int SZ_32    = BATCH * 64 * 34 * 36;
constexpr int OFF_32B  = OFF_32A + SZ_32;
constexpr int OFF_16A  = OFF_32B + SZ_32;           // cap 128
constexpr int SZ_16    = BATCH * 128 * 18 * 20;
constexpr int OFF_16B  = OFF_16A + SZ_16;
constexpr int OFF_8A   = OFF_16B + SZ_16;           // NHWC [4][10][10][256]
constexpr int SZ_8     = BATCH * 10 * 10 * 256;
constexpr int OFF_8B   = OFF_8A + SZ_8;
constexpr int OFF_4A   = OFF_8B + SZ_8;             // NHWC [4][6][6][512]
constexpr int SZ_4     = BATCH * 6 * 6 * 512;
constexpr int OFF_4B   = OFF_4A + SZ_4;
constexpr int OFF_2A   = OFF_4B + SZ_4;             // NHWC [4][4][4][512]
constexpr int SZ_2     = BATCH * 4 * 4 * 512;
constexpr int OFF_2B   = OFF_2A + SZ_2;
constexpr int OFF_FCS0 = OFF_2B + SZ_2;             // [4][4096]
constexpr int OFF_FCS1 = OFF_FCS0 + BATCH * 4096;

constexpr int M0  = OFF_FCS1 + BATCH * 4096;
constexpr int M1  = M0  + BATCH * 64  * 32 * 32;
constexpr int M2  = M1  + BATCH * 64  * 32 * 32;
constexpr int M3  = M2  + BATCH * 128 * 16 * 16;
constexpr int M4  = M3  + BATCH * 128 * 16 * 16;
constexpr int M5  = M4  + BATCH * 256 * 8 * 8;
constexpr int M6  = M5  + BATCH * 256 * 8 * 8;
constexpr int M7  = M6  + BATCH * 256 * 8 * 8;
constexpr int M8  = M7  + BATCH * 512 * 4 * 4;
constexpr int M9  = M8  + BATCH * 512 * 4 * 4;
constexpr int M10 = M9  + BATCH * 512 * 4 * 4;
constexpr int M11 = M10 + BATCH * 512 * 2 * 2;
constexpr int M12 = M11 + BATCH * 512 * 2 * 2;
constexpr int MF0 = M12 + BATCH * 512 * 2 * 2;
constexpr int MF1 = MF0 + BATCH * 4096;
constexpr int TOTAL_BUF = MF1 + BATCH * 4096;

__device__ __align__(16) float g_buf[TOTAL_BUF];

// transposed weights [co][tap][ci] for conv layers 4..12
constexpr long WT4  = 0;
constexpr long WT5  = WT4  + 256L * 128 * 9;
constexpr long WT6  = WT5  + 256L * 256 * 9;
constexpr long WT7  = WT6  + 256L * 256 * 9;
constexpr long WT8  = WT7  + 512L * 256 * 9;
constexpr long WT9  = WT8  + 512L * 512 * 9;
constexpr long WT10 = WT9  + 512L * 512 * 9;
constexpr long WT11 = WT10 + 512L * 512 * 9;
constexpr long WT12 = WT11 + 512L * 512 * 9;
constexpr long WT_TOTAL = WT12 + 512L * 512 * 9;
__device__ __align__(16) float g_wt[WT_TOTAL];

// ---------------- software grid barrier (monotonic epochs) ----------------
__device__ unsigned g_cnt = 0;
__device__ unsigned g_rel = 0;

DEV_INLINE void gsync(unsigned e) {
    __syncthreads();
    if (threadIdx.x == 0) {
        __threadfence();
        unsigned v = atomicAdd(&g_cnt, 1u);
        if (v + 1u == e * (unsigned)NB) {
            atomicExch(&g_rel, e);
        } else {
            while (atomicAdd(&g_rel, 0u) < e) { }
        }
        __threadfence();
    }
    __syncthreads();
}

// ---------------- multi-compartment LIF (K=2), exact ----------------------
DEV_INLINE float lif_fire(float* memp, float syn, float thr, float leak) {
    float m = leak * (*memp) + syn;
    float e0 = m / thr          - 1.0f;
    float o0 = 1.0f - m / (2.0f * thr);
    float e1 = m / (2.0f * thr) - 1.0f;
    float o1 = 1.0f - m / (4.0f * thr);
    float v = 0.0f;
    if (e0 > 0.0f && o0 >= 0.0f) v = 1.0f;
    if (e1 > 0.0f && o1 >= 0.0f) v = 2.0f;
    *memp = m - thr * v;
    return v;
}

// ---------------- pre-kernels ---------------------------------------------
__global__ void k_zero(float* __restrict__ dout) {
    int i = blockIdx.x * blockDim.x + threadIdx.x;
    if (i < TOTAL_BUF) g_buf[i] = 0.0f;
    if (i < BATCH * 10) dout[i] = 0.0f;
}

__global__ void k_pad_x(const float* __restrict__ x) {
    int idx = blockIdx.x * blockDim.x + threadIdx.x;
    if (idx >= BATCH * 3 * 32 * 32) return;
    int xx = idx & 31;
    int y  = (idx >> 5) & 31;
    int c  = (idx >> 10) % 3;
    int b  = idx / (3 * 1024);
    g_buf[OFF_X + ((b * 3 + c) * 34 + (y + 1)) * 36 + (xx + 1)] = x[idx];
}

struct WP { const float* p[9]; };
__global__ void k_wtrans_all(WP wp) {
    __shared__ float s[4608];
    const int CINs[9]  = {128, 256, 256, 256, 512, 512, 512, 512, 512};
    const int COUTs[9] = {256, 256, 256, 512, 512, 512, 512, 512, 512};
    const long OFFs[9] = {WT4, WT5, WT6, WT7, WT8, WT9, WT10, WT11, WT12};
    int l  = blockIdx.y;
    int co = blockIdx.x;
    int CIN = CINs[l];
    if (co >= COUTs[l]) return;
    const float* src = wp.p[l] + (long)co * CIN * 9;
    float* dst = g_wt + OFFs[l] + (long)co * CIN * 9;
    int n = CIN * 9;
    for (int i = threadIdx.x; i < n; i += 256) s[i] = src[i];
    __syncthreads();
    for (int i = threadIdx.x; i < n; i += 256) {
        int ci = i % CIN, t = i / CIN;
        dst[i] = s[ci * 9 + t];
    }
}

// ---------------- persistent device ops -----------------------------------
// conv flavor T: NCHW, one (co, part) job per block round, smem weights.
template<int CIN, int CICAP, int S, int COUT, int PARTS>
DEV_INLINE void conv_T(int in_off, const float* __restrict__ w,
                       int mem_off, int out_off,
                       const float* __restrict__ thrp, const float* __restrict__ leakp,
                       float* sw) {
    constexpr int RS = S + 4, ROWS = S + 2, NX = S / 4;
    constexpr int PLANE = ROWS * RS;
    constexpr int P = BATCH * S * NX;
    constexpr int TPJ = (P + PARTS - 1) / PARTS;
    float thr = __ldg(thrp), leak = __ldg(leakp);

    for (int job = blockIdx.x; job < COUT * PARTS; job += NB) {
        int co = job / PARTS, part = job % PARTS;
        __syncthreads();
        for (int i = threadIdx.x; i < CIN * 9; i += NT)
            sw[(i / 9) * 12 + (i % 9)] = __ldg(w + (long)co * CIN * 9 + i);
        __syncthreads();

        int tid = part * TPJ + threadIdx.x;
        if (threadIdx.x < TPJ && tid < P) {
            int x0 = (tid % NX) * 4;
            int y  = (tid / NX) % S;
            int b  = tid / (NX * S);
            const float* ip = g_buf + in_off + (long)b * CICAP * PLANE + y * RS + x0;
            float acc[4] = {0.f, 0.f, 0.f, 0.f};
            for (int ci = 0; ci < CIN; ci++) {
                const float* p = ip + ci * PLANE;
                float r[3][8];
#pragma unroll
                for (int rr = 0; rr < 3; rr++) {
                    float4 a = __ldg((const float4*)(p + rr * RS));
                    float4 c = __ldg((const float4*)(p + rr * RS + 4));
                    r[rr][0] = a.x; r[rr][1] = a.y; r[rr][2] = a.z; r[rr][3] = a.w;
                    r[rr][4] = c.x; r[rr][5] = c.y; r[rr][6] = c.z; r[rr][7] = c.w;
                }
                float4 wa = *(const float4*)(sw + ci * 12);
                float4 wb = *(const float4*)(sw + ci * 12 + 4);
                float4 wc = *(const float4*)(sw + ci * 12 + 8);
                float wv[9] = {wa.x, wa.y, wa.z, wa.w, wb.x, wb.y, wb.z, wb.w, wc.x};
#pragma unroll
                for (int t = 0; t < 4; t++)
                    acc[t] += wv[0]*r[0][t] + wv[1]*r[0][t+1] + wv[2]*r[0][t+2]
                            + wv[3]*r[1][t] + wv[4]*r[1][t+1] + wv[5]*r[1][t+2]
                            + wv[6]*r[2][t] + wv[7]*r[2][t+1] + wv[8]*r[2][t+2];
            }
            long mbase = (((long)b * COUT + co) * S + y) * S + x0;
            long obase = (((long)b * COUT + co) * ROWS + (y + 1)) * RS + (x0 + 1);
#pragma unroll
            for (int t = 0; t < 4; t++)
                g_buf[out_off + obase + t] =
                    lif_fire(&g_buf[mem_off + mbase + t], acc[t], thr, leak);
        }
    }
}

// conv flavor W: NHWC, warp per (b,co,row), lanes own 4 channels (float4).
template<int CIN, int CST, int S, int COUT>
DEV_INLINE void conv_W(int in_off, long wt_off, int mem_off, int out_off,
                       const float* __restrict__ thrp, const float* __restrict__ leakp) {
    constexpr int SP = S + 2;
    int lane = threadIdx.x & 31;
    int wg0 = blockIdx.x * (NT / 32) + (threadIdx.x >> 5);
    float thr = __ldg(thrp), leak = __ldg(leakp);

    for (int gw = wg0; gw < BATCH * COUT * S; gw += NW) {
        int y  = gw % S;
        int co = (gw / S) % COUT;
        int b  = gw / (S * COUT);
        const float* wq = g_wt + wt_off + (long)co * CIN * 9;
        float acc[S];
#pragma unroll
        for (int t = 0; t < S; t++) acc[t] = 0.0f;

#pragma unroll
        for (int it = 0; it < CIN / 128; it++) {
            int cb = it * 128 + lane * 4;
            float4 wv[9];
#pragma unroll
            for (int t = 0; t < 9; t++)
                wv[t] = __ldg((const float4*)(wq + t * CIN + cb));
#pragma unroll
            for (int rr = 0; rr < 3; rr++) {
                const float* rp = g_buf + in_off + ((long)(b * SP + y + rr) * SP) * CST + cb;
#pragma unroll
                for (int j = 0; j < SP; j++) {
                    float4 a = __ldg((const float4*)(rp + j * CST));
#pragma unroll
                    for (int dx = 0; dx < 3; dx++) {
                        int t = j - dx;
                        if (t >= 0 && t < S) {
                            float4 wt = wv[rr * 3 + dx];
                            acc[t] += a.x*wt.x + a.y*wt.y + a.z*wt.z + a.w*wt.w;
                        }
                    }
                }
            }
        }
#pragma unroll
        for (int t = 0; t < S; t++)
#pragma unroll
            for (int o = 16; o; o >>= 1)
                acc[t] += __shfl_xor_sync(0xffffffffu, acc[t], o);

        if (lane == 0) {
#pragma unroll
            for (int t = 0; t < S; t++) {
                long midx = (((long)b * S + y) * S + t) * COUT + co;
                long oidx = (((long)b * SP + (y + 1)) * SP + (t + 1)) * (long)COUT + co;
                g_buf[out_off + oidx] =
                    lif_fire(&g_buf[mem_off + midx], acc[t], thr, leak);
            }
        }
    }
}

// conv flavor W2: S=2, warp per (b,co), full image.
template<int CIN>
DEV_INLINE void conv_W2(int in_off, long wt_off, int mem_off, int out_off,
                        const float* __restrict__ thrp, const float* __restrict__ leakp) {
    constexpr int CST = 512, SP = 4, COUT = 512;
    int lane = threadIdx.x & 31;
    int wg0 = blockIdx.x * (NT / 32) + (threadIdx.x >> 5);
    float thr = __ldg(thrp), leak = __ldg(leakp);

    for (int gw = wg0; gw < BATCH * COUT; gw += NW) {
        int co = gw % COUT;
        int b  = gw / COUT;
        const float* wq = g_wt + wt_off + (long)co * CIN * 9;
        float acc[2][2] = {{0.f, 0.f}, {0.f, 0.f}};

#pragma unroll
        for (int it = 0; it < CIN / 128; it++) {
            int cb = it * 128 + lane * 4;
            float4 wv[9];
#pragma unroll
            for (int t = 0; t < 9; t++)
                wv[t] = __ldg((const float4*)(wq + t * CIN + cb));
#pragma unroll
            for (int iy = 0; iy < SP; iy++) {
                const float* rp = g_buf + in_off + ((long)(b * SP + iy) * SP) * CST + cb;
#pragma unroll
                for (int ix = 0; ix < SP; ix++) {
                    float4 a = __ldg((const float4*)(rp + ix * CST));
#pragma unroll
                    for (int oy = 0; oy < 2; oy++) {
                        int dy = iy - oy;
                        if (dy < 0 || dy > 2) continue;
#pragma unroll
                        for (int ox = 0; ox < 2; ox++) {
                            int dx = ix - ox;
                            if (dx < 0 || dx > 2) continue;
                            float4 wt = wv[dy * 3 + dx];
                            acc[oy][ox] += a.x*wt.x + a.y*wt.y + a.z*wt.z + a.w*wt.w;
                        }
                    }
                }
            }
        }
#pragma unroll
        for (int oy = 0; oy < 2; oy++)
#pragma unroll
            for (int ox = 0; ox < 2; ox++)
#pragma unroll
                for (int o = 16; o; o >>= 1)
                    acc[oy][ox] += __shfl_xor_sync(0xffffffffu, acc[oy][ox], o);

        if (lane == 0) {
#pragma unroll
            for (int oy = 0; oy < 2; oy++)
#pragma unroll
                for (int ox = 0; ox < 2; ox++) {
                    long midx = (((long)b * 2 + oy) * 2 + ox) * COUT + co;
                    long oidx = (((long)b * SP + (oy + 1)) * SP + (ox + 1)) * (long)COUT + co;
                    g_buf[out_off + oidx] =
                        lif_fire(&g_buf[mem_off + midx], acc[oy][ox], thr, leak);
                }
        }
    }
}

// pools (element-stride loops)
template<int C, int S, int CI, int CO>   // NCHW(S) -> NCHW(S/2)
DEV_INLINE void pool_cc(int in_off, int out_off) {
    constexpr int SO = S / 2, RSI = S + 4, ROWSI = S + 2, RSO = SO + 4, ROWSO = SO + 2;
    for (int idx = blockIdx.x * NT + threadIdx.x; idx < BATCH * C * SO * SO; idx += NB * NT) {
        int x = idx % SO, y = (idx / SO) % SO;
        int c = (idx / (SO * SO)) % C, b = idx / (SO * SO * C);
        const float* p = g_buf + in_off + ((long)(b * CI + c) * ROWSI + 2 * y + 1) * RSI + 2 * x + 1;
        float v = 0.25f * (p[0] + p[1] + p[RSI] + p[RSI + 1]);
        g_buf[out_off + ((long)(b * CO + c) * ROWSO + y + 1) * RSO + x + 1] = v;
    }
}

template<int C, int S, int CI, int CSTO>  // NCHW(S) -> NHWC(S/2)
DEV_INLINE void pool_cn(int in_off, int out_off) {
    constexpr int SO = S / 2, RSI = S + 4, ROWSI = S + 2, SPO = SO + 2;
    for (int idx = blockIdx.x * NT + threadIdx.x; idx < BATCH * C * SO * SO; idx += NB * NT) {
        int c = idx % C;
        int x = (idx / C) % SO, y = (idx / (C * SO)) % SO, b = idx / (C * SO * SO);
        const float* p = g_buf + in_off + ((long)(b * CI + c) * ROWSI + 2 * y + 1) * RSI + 2 * x + 1;
        float v = 0.25f * (p[0] + p[1] + p[RSI] + p[RSI + 1]);
        g_buf[out_off + (((long)b * SPO + y + 1) * SPO + x + 1) * CSTO + c] = v;
    }
}

template<int C, int S, int CSTI, int CSTO>  // NHWC(S) -> NHWC(S/2)
DEV_INLINE void pool_nn(int in_off, int out_off) {
    constexpr int SO = S / 2, SPI = S + 2, SPO = SO + 2;
    for (int idx = blockIdx.x * NT + threadIdx.x; idx < BATCH * C * SO * SO; idx += NB * NT) {
        int c = idx % C;
        int x = (idx / C) % SO, y = (idx / (C * SO)) % SO, b = idx / (C * SO * SO);
        const float* p = g_buf + in_off + (((long)b * SPI + 2 * y + 1) * SPI + 2 * x + 1) * CSTI + c;
        float v = 0.25f * (p[0] + p[CSTI] + p[(long)SPI * CSTI] + p[(long)(SPI + 1) * CSTI]);
        g_buf[out_off + (((long)b * SPO + y + 1) * SPO + x + 1) * CSTO + c] = v;
    }
}

// fc0: reads NHWC padded [4][4][4][512]; flat f = c*4 + y*2 + x
DEV_INLINE void fc0_op(const float* __restrict__ W, int mem_off, int out_off,
                       const float* __restrict__ thrp, const float* __restrict__ leakp) {
    int lane = threadIdx.x & 31;
    int wg0 = blockIdx.x * (NT / 32) + (threadIdx.x >> 5);
    float thr = __ldg(thrp), leak = __ldg(leakp);
    const float* src = g_buf + OFF_2B;
    for (int o = wg0; o < 4096; o += NW) {
        float acc[4] = {0.f, 0.f, 0.f, 0.f};
        for (int c = lane; c < 512; c += 32) {
            float4 wv = __ldg((const float4*)(W + (long)o * 2048 + c * 4));
#pragma unroll
            for (int b = 0; b < 4; b++) {
                long base = ((long)(b * 16 + 5)) * 512 + c;
                float a00 = src[base], a01 = src[base + 512];
                float a10 = src[base + 4 * 512], a11 = src[base + 5 * 512];
                acc[b] += wv.x * a00 + wv.y * a01 + wv.z * a10 + wv.w * a11;
            }
        }
#pragma unroll
        for (int b = 0; b < 4; b++)
#pragma unroll
            for (int of = 16; of; of >>= 1)
                acc[b] += __shfl_xor_sync(0xffffffffu, acc[b], of);
        if (lane == 0)
#pragma unroll
            for (int b = 0; b < 4; b++)
                g_buf[out_off + (long)b * 4096 + o] =
                    lif_fire(&g_buf[mem_off + (long)b * 4096 + o], acc[b], thr, leak);
    }
}

template<int KD>
DEV_INLINE void fc4_op(const float* __restrict__ W, int in_off, int mem_off, int out_off,
                       const float* __restrict__ thrp, const float* __restrict__ leakp,
                       int OUTN) {
    int lane = threadIdx.x & 31;
    int wg0 = blockIdx.x * (NT / 32) + (threadIdx.x >> 5);
    float thr = __ldg(thrp), leak = __ldg(leakp);
    const float4* ip = (const float4*)(g_buf + in_off);
    for (int o = wg0; o < OUTN; o += NW) {
        const float4* wp = (const float4*)(W + (long)o * KD);
        float acc[4] = {0.f, 0.f, 0.f, 0.f};
        for (int k = lane; k < KD / 4; k += 32) {
            float4 wv = __ldg(wp + k);
#pragma unroll
            for (int b = 0; b < 4; b++) {
                float4 a = ip[b * (KD / 4) + k];
                acc[b] += wv.x * a.x + wv.y * a.y + wv.z * a.z + wv.w * a.w;
            }
        }
#pragma unroll
        for (int b = 0; b < 4; b++)
#pragma unroll
            for (int of = 16; of; of >>= 1)
                acc[b] += __shfl_xor_sync(0xffffffffu, acc[b], of);
        if (lane == 0)
#pragma unroll
            for (int b = 0; b < 4; b++)
                g_buf[out_off + (long)b * OUTN + o] =
                    lif_fire(&g_buf[mem_off + (long)b * OUTN + o], acc[b], thr, leak);
    }
}

DEV_INLINE void logits_op(const float* __restrict__ W, int in_off,
                          float* __restrict__ dout) {
    int lane = threadIdx.x & 31;
    int wg0 = blockIdx.x * (NT / 32) + (threadIdx.x >> 5);
    const float4* ip = (const float4*)(g_buf + in_off);
    for (int o = wg0; o < 10; o += NW) {
        const float4* wp = (const float4*)(W + (long)o * 4096);
        float acc[4] = {0.f, 0.f, 0.f, 0.f};
        for (int k = lane; k < 1024; k += 32) {
            float4 wv = __ldg(wp + k);
#pragma unroll
            for (int b = 0; b < 4; b++) {
                float4 a = ip[b * 1024 + k];
                acc[b] += wv.x * a.x + wv.y * a.y + wv.z * a.z + wv.w * a.w;
            }
        }
#pragma unroll
        for (int b = 0; b < 4; b++)
#pragma unroll
            for (int of = 16; of; of >>= 1)
                acc[b] += __shfl_xor_sync(0xffffffffu, acc[b], of);
        if (lane == 0)
#pragma unroll
            for (int b = 0; b < 4; b++)
                dout[b * 10 + o] += acc[b];
    }
}

// ---------------- the persistent network kernel ---------------------------
struct NetArgs {
    const float* w0; const float* w1; const float* w2; const float* w3;
    const float* fc0w; const float* fc1w; const float* fc2w;
    const float* thr; const float* leak;
    float* out;
};

__global__ __launch_bounds__(NT, 1)
void k_net(NetArgs a) {
    __shared__ float sw[128 * 12];
    __shared__ unsigned s_base;
    if (threadIdx.x == 0) s_base = atomicAdd(&g_rel, 0u);
    __syncthreads();
    unsigned e = s_base;

    for (int t = 0; t < 3; t++) {
        conv_T<3, 3, 32, 64, 2>(OFF_X, a.w0, M0, OFF_32A, a.thr + 0, a.leak + 0, sw);
        gsync(++e);
        conv_T<64, 64, 32, 64, 2>(OFF_32A, a.w1, M1, OFF_32B, a.thr + 1, a.leak + 1, sw);
        gsync(++e);
        pool_cc<64, 32, 64, 128>(OFF_32B, OFF_16A);
        gsync(++e);
        conv_T<64, 128, 16, 128, 1>(OFF_16A, a.w2, M2, OFF_16B, a.thr + 2, a.leak + 2, sw);
        gsync(++e);
        conv_T<128, 128, 16, 128, 1>(OFF_16B, a.w3, M3, OFF_16A, a.thr + 3, a.leak + 3, sw);
        gsync(++e);
        pool_cn<128, 16, 128, 256>(OFF_16A, OFF_8A);
        gsync(++e);
        conv_W<128, 256, 8, 256>(OFF_8A, WT4, M4, OFF_8B, a.thr + 4, a.leak + 4);
        gsync(++e);
        conv_W<256, 256, 8, 256>(OFF_8B, WT5, M5, OFF_8A, a.thr + 5, a.leak + 5);
        gsync(++e);
        conv_W<256, 256, 8, 256>(OFF_8A, WT6, M6, OFF_8B, a.thr + 6, a.leak + 6);
        gsync(++e);
        pool_nn<256, 8, 256, 512>(OFF_8B, OFF_4A);
        gsync(++e);
        conv_W<256, 512, 4, 512>(OFF_4A, WT7, M7, OFF_4B, a.thr + 7, a.leak + 7);
        gsync(++e);
        conv_W<512, 512, 4, 512>(OFF_4B, WT8, M8, OFF_4A, a.thr + 8, a.leak + 8);
        gsync(++e);
        conv_W<512, 512, 4, 512>(OFF_4A, WT9, M9, OFF_4B, a.thr + 9, a.leak + 9);
        gsync(++e);
        pool_nn<512, 4, 512, 512>(OFF_4B, OFF_2A);
        gsync(++e);
        conv_W2<512>(OFF_2A, WT10, M10, OFF_2B, a.thr + 10, a.leak + 10);
        gsync(++e);
        conv_W2<512>(OFF_2B, WT11, M11, OFF_2A, a.thr + 11, a.leak + 11);
        gsync(++e);
        conv_W2<512>(OFF_2A, WT12, M12, OFF_2B, a.thr + 12, a.leak + 12);
        gsync(++e);
        fc0_op(a.fc0w, MF0, OFF_FCS0, a.thr + 13, a.leak + 13);
        gsync(++e);
        fc4_op<4096>(a.fc1w, OFF_FCS0, MF1, OFF_FCS1, a.thr + 14, a.leak + 14, 4096);
        gsync(++e);
        logits_op(a.fc2w, OFF_FCS1, a.out);
        // no barrier needed before next step's conv0 (disjoint buffers,
        // per-thread-owned membranes; next hazard is >1 barrier away)
    }
}

// ---------------- launch --------------------------------------------------
static inline int gup(long n, int b) { return (int)((n + b - 1) / b); }

extern "C" void kernel_launch(void* const* d_in, const int* in_sizes, int n_in,
                              void* d_out, int out_size) {
    const float* x = (const float*)d_in[0];
    const float* w[13];
    for (int i = 0; i < 13; i++) w[i] = (const float*)d_in[1 + i];
    const float* fc0w = (const float*)d_in[14];
    const float* fc1w = (const float*)d_in[15];
    const float* fc2w = (const float*)d_in[16];
    const float* thr  = (const float*)d_in[17];
    const float* leak = (const float*)d_in[18];
    float* out = (float*)d_out;

    k_zero<<<gup(TOTAL_BUF, 256), 256>>>(out);
    k_pad_x<<<gup(BATCH * 3 * 1024, 256), 256>>>(x);

    WP wp;
    for (int i = 0; i < 9; i++) wp.p[i] = w[4 + i];
    k_wtrans_all<<<dim3(512, 9), 256>>>(wp);

    NetArgs a;
    a.w0 = w[0]; a.w1 = w[1]; a.w2 = w[2]; a.w3 = w[3];
    a.fc0w = fc0w; a.fc1w = fc1w; a.fc2w = fc2w;
    a.thr = thr; a.leak = leak; a.out = out;
    k_net<<<NB, NT>>>(a);
}